// round 13
// baseline (speedup 1.0000x reference)
#include <cuda_runtime.h>
#include <math.h>
#include <stdint.h>

#define T_STEPS 20
#define BATCH   1024
#define D_IN    2312
#define HID     512
#define OUTN    10
#define BJ0     0.01f
#define BETA_C  1.8f

// Eigen TensorContractionBlocking (threaded): kc = (16384-192)/64 = 253 -> floor8 = 248.
// BK=8 tiles: panel fold when (tile+1) % 31 == 0.
#define KC_PANEL 248

// ---------------- device state (no allocs allowed) ----------------
__device__ float g_hin[(size_t)T_STEPS * BATCH * HID];
__device__ float g_r1_mem[BATCH * HID];
__device__ float g_r1_b[BATCH * HID];
__device__ float g_r1_spk[2][BATCH * HID];
__device__ float g_o_mem[BATCH * OUTN];
__device__ float g_o_b[BATCH * OUTN];
__device__ float g_o_spk[2][BATCH * OUTN];
__device__ float g_alpha_r1[HID], g_ro_r1[HID];
__device__ float g_alpha_o[OUTN], g_ro_o[OUTN];

// ---------------- packed f32x2 helpers (per-half rn semantics, proven bit-safe) ----------
#define UNPACKF2(lo, hi, s) asm("mov.b64 {%0, %1}, %2;" : "=f"(lo), "=f"(hi) : "l"(s))
#define FMAF2(acc, a, b) asm("fma.rn.f32x2 %0, %1, %2, %0;" : "+l"(acc) : "l"(a), "l"(b))
#define ADDF2(d, a, b) asm("add.rn.f32x2 %0, %1, %2;" : "=l"(d) : "l"(a), "l"(b))

// ---------------- XLA:CPU GenerateVF32Exp (frozen) ----------------
__device__ __forceinline__ float xla_expf(float input) {
    const float exp_hi = 88.3762626647950f;
    const float exp_lo = -88.3762626647949f;
    const float LOG2EF = 1.44269504088896341f;
    const float C1 = 0.693359375f;
    const float C2 = -2.12194440e-4f;
    const float p0 = 1.9875691500E-4f;
    const float p1 = 1.3981999507E-3f;
    const float p2 = 8.3334519073E-3f;
    const float p3 = 4.1665795894E-2f;
    const float p4 = 1.6666665459E-1f;
    const float p5 = 5.0000001201E-1f;

    float x = fminf(input, exp_hi);
    x = fmaxf(x, exp_lo);
    float fx = floorf(__fmaf_rn(x, LOG2EF, 0.5f));
    x = __fmaf_rn(-C1, fx, x);
    x = __fmaf_rn(-C2, fx, x);
    float z = __fmul_rn(x, x);
    float y = __fmaf_rn(x, p0, p1);
    y = __fmaf_rn(y, x, p2);
    y = __fmaf_rn(y, x, p3);
    y = __fmaf_rn(y, x, p4);
    y = __fmaf_rn(y, x, p5);
    y = __fmaf_rn(y, z, x);
    y = __fadd_rn(1.0f, y);
    int mi = (int)fx;
    float sc = __int_as_float((mi + 127) << 23);
    return fmaxf(__fmul_rn(y, sc), input);
}

__global__ void init_decay(const float* __restrict__ tau_m_r1, const float* __restrict__ tau_adp_r1,
                           const float* __restrict__ tau_m_o,  const float* __restrict__ tau_adp_o) {
    int i = threadIdx.x;
    if (i < HID) {
        g_alpha_r1[i] = xla_expf(__fdiv_rn(-1.0f, tau_m_r1[i]));
        g_ro_r1[i]    = xla_expf(__fdiv_rn(-1.0f, tau_adp_r1[i]));
    }
    if (i < OUTN) {
        g_alpha_o[i]  = xla_expf(__fdiv_rn(-1.0f, tau_m_o[i]));
        g_ro_o[i]     = xla_expf(__fdiv_rn(-1.0f, tau_adp_o[i]));
    }
}

// ---------------- output-layer step body (frozen semantics; 256 threads, 32 rows) --------
// Chain per (b,o): two kc=248 panels computed as independent ILP chains; final
// fadd(p1,p2) == sequential fold since fadd(0,p1)==p1 exactly.
__device__ __forceinline__ void out_step_body(
        int s, int rowBase,
        const float* __restrict__ SP, const float* __restrict__ OPrev,
        float* __restrict__ OOut,
        const float* __restrict__ Wd2o, const float* __restrict__ bd2o,
        const float* __restrict__ d2o_mem0, float* __restrict__ out_sum,
        float (*msm)[OUTN]) {
    int tid = threadIdx.x;
    for (int p = tid; p < 32 * OUTN; p += 256) {
        int bl = p / OUTN, o = p - bl * OUTN;
        int b = rowBase + bl;
        const float4* s4 = (const float4*)(SP + (size_t)b * HID);
        const float4* w4 = (const float4*)(Wd2o + (size_t)o * HID);

        float a1 = 0.0f, a2 = 0.0f;
#pragma unroll 2
        for (int q = 0; q < 62; q++) {          // panel1 k=0..247 ; panel2 k=248..495
            float4 u = s4[q];
            float4 wa = w4[q];
            float4 v = s4[q + 62];
            float4 wb = w4[q + 62];
            a1 = __fmaf_rn(u.x, wa.x, a1);
            a1 = __fmaf_rn(u.y, wa.y, a1);
            a1 = __fmaf_rn(u.z, wa.z, a1);
            a1 = __fmaf_rn(u.w, wa.w, a1);
            a2 = __fmaf_rn(v.x, wb.x, a2);
            a2 = __fmaf_rn(v.y, wb.y, a2);
            a2 = __fmaf_rn(v.z, wb.z, a2);
            a2 = __fmaf_rn(v.w, wb.w, a2);
        }
#pragma unroll
        for (int q = 124; q < 128; q++) {       // panel2 tail k=496..511
            float4 v = s4[q];
            float4 wb = w4[q];
            a2 = __fmaf_rn(v.x, wb.x, a2);
            a2 = __fmaf_rn(v.y, wb.y, a2);
            a2 = __fmaf_rn(v.z, wb.z, a2);
            a2 = __fmaf_rn(v.w, wb.w, a2);
        }
        float acc = __fadd_rn(a1, a2);

        float oin   = __fadd_rn(acc, bd2o[o]);
        float alpha = g_alpha_o[o];
        float ro    = g_ro_o[o];
        size_t idx  = (size_t)b * OUTN + o;
        float sp    = (s == 0) ? 0.0f : OPrev[idx];
        float bprev = (s == 0) ? BJ0 : g_o_b[idx];
        float mprev = (s == 0) ? d2o_mem0[idx] : g_o_mem[idx];
        float bnew  = __fmaf_rn(ro, bprev, __fmul_rn(__fsub_rn(1.0f, ro), sp));
        float Bth   = __fmaf_rn(BETA_C, bnew, BJ0);
        float t1    = __fmaf_rn(mprev, alpha, __fmul_rn(__fsub_rn(1.0f, alpha), oin));
        float mnew  = __fmaf_rn(-Bth, sp, t1);
        float spn   = (__fsub_rn(mnew, Bth) > 0.0f) ? 1.0f : 0.0f;
        g_o_b[idx]   = bnew;
        g_o_mem[idx] = mnew;
        OOut[idx]    = spn;
        msm[bl][o]   = mnew;
    }
    __syncthreads();
    for (int p = tid; p < 32 * OUTN; p += 256) {
        int bl = p / OUTN, o = p - bl * OUTN;
        int b = rowBase + bl;
        size_t idx = (size_t)b * OUTN + o;
        if (s == 0) {
            out_sum[idx] = 0.0f;
        } else {
            float mvals[OUTN];
#pragma unroll
            for (int q = 0; q < OUTN; q++) mvals[q] = msm[bl][q];
            float mx = mvals[0];
#pragma unroll
            for (int q = 1; q < OUTN; q++) mx = fmaxf(mx, mvals[q]);
            float e[OUTN];
#pragma unroll
            for (int q = 0; q < OUTN; q++) e[q] = xla_expf(__fsub_rn(mvals[q], mx));
            float se = 0.0f;
#pragma unroll
            for (int q = 0; q < OUTN; q++) se = __fadd_rn(se, e[q]);
            out_sum[idx] = __fadd_rn(out_sum[idx], __fdiv_rn(e[o], se));
        }
    }
}

// ---------------- Kernel 1: i2h GEMM, f32x2, duplicated-B smem, kc=248 panels ------------
// M=20480, N=512, K=2312. BM=128, BN=64, BK=8, 256 threads, 4 M-pairs x 4 N per thread.
__global__ __launch_bounds__(256) void gemm_i2h(const float* __restrict__ A,
                                                const float* __restrict__ W,
                                                const float* __restrict__ bias) {
    const int K = D_IN;
    __shared__ __align__(16) float  As[2][8][132];
    __shared__ __align__(16) float2 BsD[2][8][66];   // duplicated {b,b} pairs

    int bm = blockIdx.y * 128;
    int bn = blockIdx.x * 64;
    int tid = threadIdx.x;
    int wid = tid >> 5, lane = tid & 31;
    int m0 = (wid & 3) * 32 + (lane & 3) * 8;
    int n0 = (wid >> 2) * 32 + (lane >> 2) * 4;

    int alr = tid >> 1, alc = (tid & 1) * 4;
    int blr = (tid & 127) >> 1, blc = ((tid & 127) & 1) * 4;
    const float* Aptr = A + (size_t)(bm + alr) * K + alc;
    const float* Wptr = W + (size_t)(bn + blr) * K + blc;

    uint64_t accT[4][4], accP[4][4];
#pragma unroll
    for (int p = 0; p < 4; p++)
#pragma unroll
        for (int j = 0; j < 4; j++) { accT[p][j] = 0ull; accP[p][j] = 0ull; }

    const int NT = K / 8;   // 289

    float4 av = *(const float4*)(Aptr);
    float4 bv = make_float4(0.f, 0.f, 0.f, 0.f);
    if (tid < 128) bv = *(const float4*)(Wptr);
    As[0][alc + 0][alr] = av.x; As[0][alc + 1][alr] = av.y;
    As[0][alc + 2][alr] = av.z; As[0][alc + 3][alr] = av.w;
    if (tid < 128) {
        BsD[0][blc + 0][blr] = make_float2(bv.x, bv.x);
        BsD[0][blc + 1][blr] = make_float2(bv.y, bv.y);
        BsD[0][blc + 2][blr] = make_float2(bv.z, bv.z);
        BsD[0][blc + 3][blr] = make_float2(bv.w, bv.w);
    }
    __syncthreads();

    for (int it = 0; it < NT; ++it) {
        int buf = it & 1;
        if (it + 1 < NT) {
            av = *(const float4*)(Aptr + (it + 1) * 8);
            if (tid < 128) bv = *(const float4*)(Wptr + (it + 1) * 8);
        }
#pragma unroll
        for (int kk = 0; kk < 8; kk++) {
            ulonglong2 aa0 = *(const ulonglong2*)&As[buf][kk][m0];
            ulonglong2 aa1 = *(const ulonglong2*)&As[buf][kk][m0 + 4];
            ulonglong2 bb0 = *(const ulonglong2*)&BsD[buf][kk][n0];
            ulonglong2 bb1 = *(const ulonglong2*)&BsD[buf][kk][n0 + 2];
            uint64_t ap0 = aa0.x, ap1 = aa0.y, ap2 = aa1.x, ap3 = aa1.y;
            FMAF2(accP[0][0], ap0, bb0.x); FMAF2(accP[0][1], ap0, bb0.y);
            FMAF2(accP[0][2], ap0, bb1.x); FMAF2(accP[0][3], ap0, bb1.y);
            FMAF2(accP[1][0], ap1, bb0.x); FMAF2(accP[1][1], ap1, bb0.y);
            FMAF2(accP[1][2], ap1, bb1.x); FMAF2(accP[1][3], ap1, bb1.y);
            FMAF2(accP[2][0], ap2, bb0.x); FMAF2(accP[2][1], ap2, bb0.y);
            FMAF2(accP[2][2], ap2, bb1.x); FMAF2(accP[2][3], ap2, bb1.y);
            FMAF2(accP[3][0], ap3, bb0.x); FMAF2(accP[3][1], ap3, bb0.y);
            FMAF2(accP[3][2], ap3, bb1.x); FMAF2(accP[3][3], ap3, bb1.y);
        }
        if (((it + 1) % 31) == 0) {
#pragma unroll
            for (int p = 0; p < 4; p++)
#pragma unroll
                for (int j = 0; j < 4; j++) {
                    ADDF2(accT[p][j], accT[p][j], accP[p][j]);
                    accP[p][j] = 0ull;
                }
        }
        if (it + 1 < NT) {
            int nb = buf ^ 1;
            As[nb][alc + 0][alr] = av.x; As[nb][alc + 1][alr] = av.y;
            As[nb][alc + 2][alr] = av.z; As[nb][alc + 3][alr] = av.w;
            if (tid < 128) {
                BsD[nb][blc + 0][blr] = make_float2(bv.x, bv.x);
                BsD[nb][blc + 1][blr] = make_float2(bv.y, bv.y);
                BsD[nb][blc + 2][blr] = make_float2(bv.z, bv.z);
                BsD[nb][blc + 3][blr] = make_float2(bv.w, bv.w);
            }
            __syncthreads();
        }
    }
#pragma unroll
    for (int p = 0; p < 4; p++)
#pragma unroll
        for (int j = 0; j < 4; j++) ADDF2(accT[p][j], accT[p][j], accP[p][j]);

#pragma unroll
    for (int p = 0; p < 4; p++) {
        int r0 = bm + m0 + 2 * p;
#pragma unroll
        for (int j = 0; j < 4; j++) {
            int n = bn + n0 + j;
            float lo, hi;
            UNPACKF2(lo, hi, accT[p][j]);
            g_hin[(size_t)r0 * HID + n]       = __fadd_rn(lo, bias[n]);
            g_hin[(size_t)(r0 + 1) * HID + n] = __fadd_rn(hi, bias[n]);
        }
    }
}

// ---------------- Kernel 2: FUSED step — r1 GEMM+LIF blocks + out(t-1) blocks -----------
// grid = 128 GEMM blocks (8 N x 16 M, 64x64 tiles) + 32 out blocks. 256 threads.
__global__ __launch_bounds__(256) void step_fused(int t,
        const float* __restrict__ spike_prev_arg, float* __restrict__ spike_out_arg,
        const float* __restrict__ Wh2h, const float* __restrict__ bh2h,
        const float* __restrict__ r1_mem0,
        const float* __restrict__ o_prev_arg, float* __restrict__ o_out_arg,
        const float* __restrict__ Wd2o, const float* __restrict__ bd2o,
        const float* __restrict__ d2o_mem0, float* __restrict__ out_sum) {
    __shared__ __align__(16) float  As[2][8][68];
    __shared__ __align__(16) float2 BsD[2][8][66];
    __shared__ float msm[32][OUTN];

    const float* SP = spike_prev_arg ? spike_prev_arg : g_r1_spk[(t + 1) & 1];

    int bx = blockIdx.x;
    if (bx >= 128) {
        // ---- out block: output-layer step s = t-1 (spikes(s) == SP) ----
        if (t == 0) return;
        int s = t - 1;
        const float* OPrev = o_prev_arg ? o_prev_arg : g_o_spk[(s + 1) & 1];
        float*       OOut  = o_out_arg  ? o_out_arg  : g_o_spk[s & 1];
        out_step_body(s, (bx - 128) * 32, SP, OPrev, OOut,
                      Wd2o, bd2o, d2o_mem0, out_sum, msm);
        return;
    }

    // ---- r1 GEMM + LIF block ----
    float* SO = spike_out_arg ? spike_out_arg : g_r1_spk[t & 1];

    int bn = (bx & 7) * 64;
    int bm = (bx >> 3) * 64;
    int tid = threadIdx.x;
    int wid = tid >> 5, lane = tid & 31;
    int m0 = (wid & 3) * 16 + (lane & 3) * 4;
    int n0 = (wid >> 2) * 32 + (lane >> 2) * 4;

    int u = tid & 127;
    int lr = u >> 1, lc = (u & 1) * 4;
    bool loadB = (tid >= 128);
    const float* src = loadB ? (Wh2h + (size_t)(bn + lr) * HID + lc)
                             : (SP   + (size_t)(bm + lr) * HID + lc);

    uint64_t accT[2][4], accP[2][4];
#pragma unroll
    for (int p = 0; p < 2; p++)
#pragma unroll
        for (int j = 0; j < 4; j++) { accT[p][j] = 0ull; accP[p][j] = 0ull; }

    const int NT = HID / 8;   // 64

    float4 v = *(const float4*)(src);
    if (loadB) {
        BsD[0][lc + 0][lr] = make_float2(v.x, v.x);
        BsD[0][lc + 1][lr] = make_float2(v.y, v.y);
        BsD[0][lc + 2][lr] = make_float2(v.z, v.z);
        BsD[0][lc + 3][lr] = make_float2(v.w, v.w);
    } else {
        As[0][lc + 0][lr] = v.x; As[0][lc + 1][lr] = v.y;
        As[0][lc + 2][lr] = v.z; As[0][lc + 3][lr] = v.w;
    }
    __syncthreads();

    for (int it = 0; it < NT; ++it) {
        int buf = it & 1;
        if (it + 1 < NT) v = *(const float4*)(src + (it + 1) * 8);
#pragma unroll
        for (int kk = 0; kk < 8; kk++) {
            ulonglong2 aa = *(const ulonglong2*)&As[buf][kk][m0];
            ulonglong2 bb0 = *(const ulonglong2*)&BsD[buf][kk][n0];
            ulonglong2 bb1 = *(const ulonglong2*)&BsD[buf][kk][n0 + 2];
            uint64_t ap0 = aa.x, ap1 = aa.y;
            FMAF2(accP[0][0], ap0, bb0.x); FMAF2(accP[0][1], ap0, bb0.y);
            FMAF2(accP[0][2], ap0, bb1.x); FMAF2(accP[0][3], ap0, bb1.y);
            FMAF2(accP[1][0], ap1, bb0.x); FMAF2(accP[1][1], ap1, bb0.y);
            FMAF2(accP[1][2], ap1, bb1.x); FMAF2(accP[1][3], ap1, bb1.y);
        }
        if (((it + 1) % 31) == 0) {   // k = 248, 496
#pragma unroll
            for (int p = 0; p < 2; p++)
#pragma unroll
                for (int j = 0; j < 4; j++) {
                    ADDF2(accT[p][j], accT[p][j], accP[p][j]);
                    accP[p][j] = 0ull;
                }
        }
        if (it + 1 < NT) {
            int nb = buf ^ 1;
            if (loadB) {
                BsD[nb][lc + 0][lr] = make_float2(v.x, v.x);
                BsD[nb][lc + 1][lr] = make_float2(v.y, v.y);
                BsD[nb][lc + 2][lr] = make_float2(v.z, v.z);
                BsD[nb][lc + 3][lr] = make_float2(v.w, v.w);
            } else {
                As[nb][lc + 0][lr] = v.x; As[nb][lc + 1][lr] = v.y;
                As[nb][lc + 2][lr] = v.z; As[nb][lc + 3][lr] = v.w;
            }
            __syncthreads();
        }
    }
#pragma unroll
    for (int p = 0; p < 2; p++)
#pragma unroll
        for (int j = 0; j < 4; j++) ADDF2(accT[p][j], accT[p][j], accP[p][j]);

    // LIF epilogue (frozen contracted semantics)
#pragma unroll
    for (int j = 0; j < 4; j++) {
        int n = bn + n0 + j;
        float alpha = g_alpha_r1[n];
        float ro    = g_ro_r1[n];
        float one_m_alpha = __fsub_rn(1.0f, alpha);
        float one_m_ro    = __fsub_rn(1.0f, ro);
        float bias  = bh2h[n];
#pragma unroll
        for (int p = 0; p < 2; p++) {
            float lo, hi;
            UNPACKF2(lo, hi, accT[p][j]);
#pragma unroll
            for (int h = 0; h < 2; h++) {
                float accv = h ? hi : lo;
                int m = bm + m0 + 2 * p + h;
                size_t idx = (size_t)m * HID + n;
                float hin   = __fadd_rn(__fadd_rn(g_hin[((size_t)m * T_STEPS + t) * HID + n],
                                                  accv), bias);
                float sp    = SP[idx];
                float bprev = (t == 0) ? BJ0 : g_r1_b[idx];
                float mprev = (t == 0) ? r1_mem0[idx] : g_r1_mem[idx];
                float bnew  = __fmaf_rn(ro, bprev, __fmul_rn(one_m_ro, sp));
                float Bth   = __fmaf_rn(BETA_C, bnew, BJ0);
                float t1    = __fmaf_rn(mprev, alpha, __fmul_rn(one_m_alpha, hin));
                float mnew  = __fmaf_rn(-Bth, sp, t1);
                float spn   = (__fsub_rn(mnew, Bth) > 0.0f) ? 1.0f : 0.0f;
                g_r1_b[idx]   = bnew;
                g_r1_mem[idx] = mnew;
                SO[idx]       = spn;
            }
        }
    }
}

// ---------------- Kernel 3: tail output step (s = 19), grid 32 x 256 ----------------
__global__ __launch_bounds__(256) void step_out_tail(int s,
        const float* __restrict__ r1_spk_arg,
        const float* __restrict__ o_prev_arg, float* __restrict__ o_out_arg,
        const float* __restrict__ Wd2o, const float* __restrict__ bd2o,
        const float* __restrict__ d2o_mem0, float* __restrict__ out_sum) {
    __shared__ float msm[32][OUTN];
    const float* SP    = r1_spk_arg ? r1_spk_arg : g_r1_spk[s & 1];
    const float* OPrev = o_prev_arg ? o_prev_arg : g_o_spk[(s + 1) & 1];
    float*       OOut  = o_out_arg  ? o_out_arg  : g_o_spk[s & 1];
    out_step_body(s, blockIdx.x * 32, SP, OPrev, OOut,
                  Wd2o, bd2o, d2o_mem0, out_sum, msm);
}

// ---------------- launch ----------------
extern "C" void kernel_launch(void* const* d_in, const int* in_sizes, int n_in,
                              void* d_out, int out_size) {
    const float* x          = (const float*)d_in[0];
    const float* W_i2h      = (const float*)d_in[1];
    const float* b_i2h      = (const float*)d_in[2];
    const float* W_h2h      = (const float*)d_in[3];
    const float* b_h2h      = (const float*)d_in[4];
    const float* W_d2o      = (const float*)d_in[5];
    const float* b_d2o      = (const float*)d_in[6];
    const float* tau_adp_r1 = (const float*)d_in[7];
    const float* tau_m_r1   = (const float*)d_in[8];
    const float* tau_adp_o  = (const float*)d_in[9];
    const float* tau_m_o    = (const float*)d_in[10];
    const float* r1_mem0    = (const float*)d_in[11];
    const float* r1_spike0  = (const float*)d_in[12];
    const float* d2o_mem0   = (const float*)d_in[13];
    float* out = (float*)d_out;

    const long long SUMN = (long long)BATCH * OUTN;
    const long long R1N  = (long long)T_STEPS * BATCH * HID;
    const long long ON   = (long long)T_STEPS * BATCH * OUTN;
    const bool full = ((long long)out_size >= SUMN + R1N + ON);
    float* out_r1 = full ? out + SUMN : (float*)nullptr;
    float* out_o  = full ? out + SUMN + R1N : (float*)nullptr;

    init_decay<<<1, HID>>>(tau_m_r1, tau_adp_r1, tau_m_o, tau_adp_o);

    gemm_i2h<<<dim3(HID / 64, (T_STEPS * BATCH) / 128), 256>>>(x, W_i2h, b_i2h);

    for (int t = 0; t < T_STEPS; t++) {
        const float* spPrev = (t == 0) ? r1_spike0
                              : (full ? out_r1 + (size_t)(t - 1) * BATCH * HID : (float*)nullptr);
        float* spOut = full ? out_r1 + (size_t)t * BATCH * HID : (float*)nullptr;

        int s = t - 1;  // output-layer step performed inside this launch (skipped at t=0)
        const float* oPrev = (s <= 0) ? (float*)nullptr
                              : (full ? out_o + (size_t)(s - 1) * BATCH * OUTN : (float*)nullptr);
        float* oOut = (s < 0) ? (float*)nullptr
                      : (full ? out_o + (size_t)s * BATCH * OUTN : (float*)nullptr);

        step_fused<<<160, 256>>>(t, spPrev, spOut, W_h2h, b_h2h, r1_mem0,
                                 oPrev, oOut, W_d2o, b_d2o, d2o_mem0, out);
    }

    {   // tail: output-layer step s = 19
        int s = T_STEPS - 1;
        const float* spArg = full ? out_r1 + (size_t)s * BATCH * HID : (float*)nullptr;
        const float* oPrev = full ? out_o + (size_t)(s - 1) * BATCH * OUTN : (float*)nullptr;
        float* oOut = full ? out_o + (size_t)s * BATCH * OUTN : (float*)nullptr;
        step_out_tail<<<32, 256>>>(s, spArg, oPrev, oOut, W_d2o, b_d2o, d2o_mem0, out);
    }
}

// round 14
// speedup vs baseline: 1.0811x; 1.0811x over previous
#include <cuda_runtime.h>
#include <math.h>
#include <stdint.h>

#define T_STEPS 20
#define BATCH   1024
#define D_IN    2312
#define HID     512
#define OUTN    10
#define BJ0     0.01f
#define BETA_C  1.8f
#define NBLK    148          // persistent grid: one block per SM, single wave

// Eigen TensorContractionBlocking (threaded): kc = (16384-192)/64 = 253 -> floor8 = 248.
// BK=8 tiles: panel fold when (tile+1) % 31 == 0.
#define KC_PANEL 248

// ---------------- device state (no allocs allowed) ----------------
__device__ float g_hin[(size_t)T_STEPS * BATCH * HID];
__device__ float g_r1_mem[BATCH * HID];
__device__ float g_r1_b[BATCH * HID];
__device__ float g_r1_spk[2][BATCH * HID];
__device__ float g_o_mem[BATCH * OUTN];
__device__ float g_o_b[BATCH * OUTN];
__device__ float g_o_spk[2][BATCH * OUTN];
__device__ float g_alpha_r1[HID], g_ro_r1[HID];
__device__ float g_alpha_o[OUTN], g_ro_o[OUTN];
__device__ unsigned g_bar;

// ---------------- packed f32x2 helpers (per-half rn semantics, proven bit-safe) ----------
#define UNPACKF2(lo, hi, s) asm("mov.b64 {%0, %1}, %2;" : "=f"(lo), "=f"(hi) : "l"(s))
#define FMAF2(acc, a, b) asm("fma.rn.f32x2 %0, %1, %2, %0;" : "+l"(acc) : "l"(a), "l"(b))
#define ADDF2(d, a, b) asm("add.rn.f32x2 %0, %1, %2;" : "=l"(d) : "l"(a), "l"(b))

// ---------------- XLA:CPU GenerateVF32Exp (frozen) ----------------
__device__ __forceinline__ float xla_expf(float input) {
    const float exp_hi = 88.3762626647950f;
    const float exp_lo = -88.3762626647949f;
    const float LOG2EF = 1.44269504088896341f;
    const float C1 = 0.693359375f;
    const float C2 = -2.12194440e-4f;
    const float p0 = 1.9875691500E-4f;
    const float p1 = 1.3981999507E-3f;
    const float p2 = 8.3334519073E-3f;
    const float p3 = 4.1665795894E-2f;
    const float p4 = 1.6666665459E-1f;
    const float p5 = 5.0000001201E-1f;

    float x = fminf(input, exp_hi);
    x = fmaxf(x, exp_lo);
    float fx = floorf(__fmaf_rn(x, LOG2EF, 0.5f));
    x = __fmaf_rn(-C1, fx, x);
    x = __fmaf_rn(-C2, fx, x);
    float z = __fmul_rn(x, x);
    float y = __fmaf_rn(x, p0, p1);
    y = __fmaf_rn(y, x, p2);
    y = __fmaf_rn(y, x, p3);
    y = __fmaf_rn(y, x, p4);
    y = __fmaf_rn(y, x, p5);
    y = __fmaf_rn(y, z, x);
    y = __fadd_rn(1.0f, y);
    int mi = (int)fx;
    float sc = __int_as_float((mi + 127) << 23);
    return fmaxf(__fmul_rn(y, sc), input);
}

__global__ void init_decay(const float* __restrict__ tau_m_r1, const float* __restrict__ tau_adp_r1,
                           const float* __restrict__ tau_m_o,  const float* __restrict__ tau_adp_o) {
    int i = threadIdx.x;
    if (i == 0) g_bar = 0u;                 // reset persistent-kernel barrier each launch
    if (i < HID) {
        g_alpha_r1[i] = xla_expf(__fdiv_rn(-1.0f, tau_m_r1[i]));
        g_ro_r1[i]    = xla_expf(__fdiv_rn(-1.0f, tau_adp_r1[i]));
    }
    if (i < OUTN) {
        g_alpha_o[i]  = xla_expf(__fdiv_rn(-1.0f, tau_m_o[i]));
        g_ro_o[i]     = xla_expf(__fdiv_rn(-1.0f, tau_adp_o[i]));
    }
}

// ---------------- Kernel 1: i2h GEMM (unchanged, bit-proven) ----------------
__global__ __launch_bounds__(256) void gemm_i2h(const float* __restrict__ A,
                                                const float* __restrict__ W,
                                                const float* __restrict__ bias) {
    const int K = D_IN;
    __shared__ __align__(16) float  As[2][8][132];
    __shared__ __align__(16) float2 BsD[2][8][66];

    int bm = blockIdx.y * 128;
    int bn = blockIdx.x * 64;
    int tid = threadIdx.x;
    int wid = tid >> 5, lane = tid & 31;
    int m0 = (wid & 3) * 32 + (lane & 3) * 8;
    int n0 = (wid >> 2) * 32 + (lane >> 2) * 4;

    int alr = tid >> 1, alc = (tid & 1) * 4;
    int blr = (tid & 127) >> 1, blc = ((tid & 127) & 1) * 4;
    const float* Aptr = A + (size_t)(bm + alr) * K + alc;
    const float* Wptr = W + (size_t)(bn + blr) * K + blc;

    uint64_t accT[4][4], accP[4][4];
#pragma unroll
    for (int p = 0; p < 4; p++)
#pragma unroll
        for (int j = 0; j < 4; j++) { accT[p][j] = 0ull; accP[p][j] = 0ull; }

    const int NT = K / 8;

    float4 av = *(const float4*)(Aptr);
    float4 bv = make_float4(0.f, 0.f, 0.f, 0.f);
    if (tid < 128) bv = *(const float4*)(Wptr);
    As[0][alc + 0][alr] = av.x; As[0][alc + 1][alr] = av.y;
    As[0][alc + 2][alr] = av.z; As[0][alc + 3][alr] = av.w;
    if (tid < 128) {
        BsD[0][blc + 0][blr] = make_float2(bv.x, bv.x);
        BsD[0][blc + 1][blr] = make_float2(bv.y, bv.y);
        BsD[0][blc + 2][blr] = make_float2(bv.z, bv.z);
        BsD[0][blc + 3][blr] = make_float2(bv.w, bv.w);
    }
    __syncthreads();

    for (int it = 0; it < NT; ++it) {
        int buf = it & 1;
        if (it + 1 < NT) {
            av = *(const float4*)(Aptr + (it + 1) * 8);
            if (tid < 128) bv = *(const float4*)(Wptr + (it + 1) * 8);
        }
#pragma unroll
        for (int kk = 0; kk < 8; kk++) {
            ulonglong2 aa0 = *(const ulonglong2*)&As[buf][kk][m0];
            ulonglong2 aa1 = *(const ulonglong2*)&As[buf][kk][m0 + 4];
            ulonglong2 bb0 = *(const ulonglong2*)&BsD[buf][kk][n0];
            ulonglong2 bb1 = *(const ulonglong2*)&BsD[buf][kk][n0 + 2];
            uint64_t ap0 = aa0.x, ap1 = aa0.y, ap2 = aa1.x, ap3 = aa1.y;
            FMAF2(accP[0][0], ap0, bb0.x); FMAF2(accP[0][1], ap0, bb0.y);
            FMAF2(accP[0][2], ap0, bb1.x); FMAF2(accP[0][3], ap0, bb1.y);
            FMAF2(accP[1][0], ap1, bb0.x); FMAF2(accP[1][1], ap1, bb0.y);
            FMAF2(accP[1][2], ap1, bb1.x); FMAF2(accP[1][3], ap1, bb1.y);
            FMAF2(accP[2][0], ap2, bb0.x); FMAF2(accP[2][1], ap2, bb0.y);
            FMAF2(accP[2][2], ap2, bb1.x); FMAF2(accP[2][3], ap2, bb1.y);
            FMAF2(accP[3][0], ap3, bb0.x); FMAF2(accP[3][1], ap3, bb0.y);
            FMAF2(accP[3][2], ap3, bb1.x); FMAF2(accP[3][3], ap3, bb1.y);
        }
        if (((it + 1) % 31) == 0) {
#pragma unroll
            for (int p = 0; p < 4; p++)
#pragma unroll
                for (int j = 0; j < 4; j++) {
                    ADDF2(accT[p][j], accT[p][j], accP[p][j]);
                    accP[p][j] = 0ull;
                }
        }
        if (it + 1 < NT) {
            int nb = buf ^ 1;
            As[nb][alc + 0][alr] = av.x; As[nb][alc + 1][alr] = av.y;
            As[nb][alc + 2][alr] = av.z; As[nb][alc + 3][alr] = av.w;
            if (tid < 128) {
                BsD[nb][blc + 0][blr] = make_float2(bv.x, bv.x);
                BsD[nb][blc + 1][blr] = make_float2(bv.y, bv.y);
                BsD[nb][blc + 2][blr] = make_float2(bv.z, bv.z);
                BsD[nb][blc + 3][blr] = make_float2(bv.w, bv.w);
            }
            __syncthreads();
        }
    }
#pragma unroll
    for (int p = 0; p < 4; p++)
#pragma unroll
        for (int j = 0; j < 4; j++) ADDF2(accT[p][j], accT[p][j], accP[p][j]);

#pragma unroll
    for (int p = 0; p < 4; p++) {
        int r0 = bm + m0 + 2 * p;
#pragma unroll
        for (int j = 0; j < 4; j++) {
            int n = bn + n0 + j;
            float lo, hi;
            UNPACKF2(lo, hi, accT[p][j]);
            g_hin[(size_t)r0 * HID + n]       = __fadd_rn(lo, bias[n]);
            g_hin[(size_t)(r0 + 1) * HID + n] = __fadd_rn(hi, bias[n]);
        }
    }
}

// ---------------- output-layer step body (frozen semantics; cross-block reads via ldcg) --
__device__ __forceinline__ void out_step_body(
        int s, int rowBase, int rows,
        const float* __restrict__ SP, const float* __restrict__ OPrev,
        float* __restrict__ OOut,
        const float* __restrict__ Wd2o, const float* __restrict__ bd2o,
        const float* __restrict__ d2o_mem0, float* __restrict__ out_sum,
        float (*msm)[OUTN]) {
    int tid = threadIdx.x;
    for (int p = tid; p < rows * OUTN; p += 256) {
        int bl = p / OUTN, o = p - bl * OUTN;
        int b = rowBase + bl;
        const float4* s4 = (const float4*)(SP + (size_t)b * HID);
        const float4* w4 = (const float4*)(Wd2o + (size_t)o * HID);

        float a1 = 0.0f, a2 = 0.0f;
#pragma unroll 2
        for (int q = 0; q < 62; q++) {
            float4 u = __ldcg(&s4[q]);
            float4 wa = w4[q];
            float4 v = __ldcg(&s4[q + 62]);
            float4 wb = w4[q + 62];
            a1 = __fmaf_rn(u.x, wa.x, a1);
            a1 = __fmaf_rn(u.y, wa.y, a1);
            a1 = __fmaf_rn(u.z, wa.z, a1);
            a1 = __fmaf_rn(u.w, wa.w, a1);
            a2 = __fmaf_rn(v.x, wb.x, a2);
            a2 = __fmaf_rn(v.y, wb.y, a2);
            a2 = __fmaf_rn(v.z, wb.z, a2);
            a2 = __fmaf_rn(v.w, wb.w, a2);
        }
#pragma unroll
        for (int q = 124; q < 128; q++) {
            float4 v = __ldcg(&s4[q]);
            float4 wb = w4[q];
            a2 = __fmaf_rn(v.x, wb.x, a2);
            a2 = __fmaf_rn(v.y, wb.y, a2);
            a2 = __fmaf_rn(v.z, wb.z, a2);
            a2 = __fmaf_rn(v.w, wb.w, a2);
        }
        float acc = __fadd_rn(a1, a2);

        float oin   = __fadd_rn(acc, bd2o[o]);
        float alpha = g_alpha_o[o];
        float ro    = g_ro_o[o];
        size_t idx  = (size_t)b * OUTN + o;
        float sp    = (s == 0) ? 0.0f : __ldcg(&OPrev[idx]);
        float bprev = (s == 0) ? BJ0 : __ldcg(&g_o_b[idx]);
        float mprev = (s == 0) ? d2o_mem0[idx] : __ldcg(&g_o_mem[idx]);
        float bnew  = __fmaf_rn(ro, bprev, __fmul_rn(__fsub_rn(1.0f, ro), sp));
        float Bth   = __fmaf_rn(BETA_C, bnew, BJ0);
        float t1    = __fmaf_rn(mprev, alpha, __fmul_rn(__fsub_rn(1.0f, alpha), oin));
        float mnew  = __fmaf_rn(-Bth, sp, t1);
        float spn   = (__fsub_rn(mnew, Bth) > 0.0f) ? 1.0f : 0.0f;
        g_o_b[idx]   = bnew;
        g_o_mem[idx] = mnew;
        OOut[idx]    = spn;
        msm[bl][o]   = mnew;
    }
    __syncthreads();
    for (int p = tid; p < rows * OUTN; p += 256) {
        int bl = p / OUTN, o = p - bl * OUTN;
        int b = rowBase + bl;
        size_t idx = (size_t)b * OUTN + o;
        if (s == 0) {
            out_sum[idx] = 0.0f;
        } else {
            float mvals[OUTN];
#pragma unroll
            for (int q = 0; q < OUTN; q++) mvals[q] = msm[bl][q];
            float mx = mvals[0];
#pragma unroll
            for (int q = 1; q < OUTN; q++) mx = fmaxf(mx, mvals[q]);
            float e[OUTN];
#pragma unroll
            for (int q = 0; q < OUTN; q++) e[q] = xla_expf(__fsub_rn(mvals[q], mx));
            float se = 0.0f;
#pragma unroll
            for (int q = 0; q < OUTN; q++) se = __fadd_rn(se, e[q]);
            out_sum[idx] = __fadd_rn(__ldcg(&out_sum[idx]), __fdiv_rn(e[o], se));
        }
    }
}

// ---------------- persistent 20-step kernel: 148 co-resident blocks, spin barrier --------
__global__ __launch_bounds__(256) void persistent_steps(
        const float* __restrict__ r1_spike0,
        const float* __restrict__ Wh2h, const float* __restrict__ bh2h,
        const float* __restrict__ r1_mem0,
        const float* __restrict__ Wd2o, const float* __restrict__ bd2o,
        const float* __restrict__ d2o_mem0, float* __restrict__ out_sum,
        float* out_r1, float* out_o) {
    __shared__ __align__(16) float  As[2][8][68];
    __shared__ __align__(16) float2 BsD[2][8][66];
    __shared__ float msm[52][OUTN];

    int bx = blockIdx.x;
    int tid = threadIdx.x;

    for (int t = 0; t < T_STEPS; t++) {
        const float* SP = (t == 0) ? r1_spike0
                          : (out_r1 ? out_r1 + (size_t)(t - 1) * BATCH * HID
                                    : g_r1_spk[(t + 1) & 1]);
        if (bx < 128) {
            // ---- r1 GEMM + LIF (frozen bit-exact path) ----
            float* SO = out_r1 ? out_r1 + (size_t)t * BATCH * HID : g_r1_spk[t & 1];
            int bn = (bx & 7) * 64;
            int bm = (bx >> 3) * 64;
            int wid = tid >> 5, lane = tid & 31;
            int m0 = (wid & 3) * 16 + (lane & 3) * 4;
            int n0 = (wid >> 2) * 32 + (lane >> 2) * 4;

            int u = tid & 127;
            int lr = u >> 1, lc = (u & 1) * 4;
            bool loadB = (tid >= 128);
            const float* srcW = Wh2h + (size_t)(bn + lr) * HID + lc;
            const float* srcS = SP   + (size_t)(bm + lr) * HID + lc;

            uint64_t accT[2][4], accP[2][4];
#pragma unroll
            for (int p = 0; p < 2; p++)
#pragma unroll
                for (int j = 0; j < 4; j++) { accT[p][j] = 0ull; accP[p][j] = 0ull; }

            const int NT = HID / 8;

            float4 v;
            if (loadB) v = *(const float4*)(srcW);
            else       v = __ldcg((const float4*)(srcS));
            if (loadB) {
                BsD[0][lc + 0][lr] = make_float2(v.x, v.x);
                BsD[0][lc + 1][lr] = make_float2(v.y, v.y);
                BsD[0][lc + 2][lr] = make_float2(v.z, v.z);
                BsD[0][lc + 3][lr] = make_float2(v.w, v.w);
            } else {
                As[0][lc + 0][lr] = v.x; As[0][lc + 1][lr] = v.y;
                As[0][lc + 2][lr] = v.z; As[0][lc + 3][lr] = v.w;
            }
            __syncthreads();

            for (int it = 0; it < NT; ++it) {
                int buf = it & 1;
                if (it + 1 < NT) {
                    if (loadB) v = *(const float4*)(srcW + (it + 1) * 8);
                    else       v = __ldcg((const float4*)(srcS + (it + 1) * 8));
                }
#pragma unroll
                for (int kk = 0; kk < 8; kk++) {
                    ulonglong2 aa = *(const ulonglong2*)&As[buf][kk][m0];
                    ulonglong2 bb0 = *(const ulonglong2*)&BsD[buf][kk][n0];
                    ulonglong2 bb1 = *(const ulonglong2*)&BsD[buf][kk][n0 + 2];
                    uint64_t ap0 = aa.x, ap1 = aa.y;
                    FMAF2(accP[0][0], ap0, bb0.x); FMAF2(accP[0][1], ap0, bb0.y);
                    FMAF2(accP[0][2], ap0, bb1.x); FMAF2(accP[0][3], ap0, bb1.y);
                    FMAF2(accP[1][0], ap1, bb0.x); FMAF2(accP[1][1], ap1, bb0.y);
                    FMAF2(accP[1][2], ap1, bb1.x); FMAF2(accP[1][3], ap1, bb1.y);
                }
                if (((it + 1) % 31) == 0) {
#pragma unroll
                    for (int p = 0; p < 2; p++)
#pragma unroll
                        for (int j = 0; j < 4; j++) {
                            ADDF2(accT[p][j], accT[p][j], accP[p][j]);
                            accP[p][j] = 0ull;
                        }
                }
                if (it + 1 < NT) {
                    int nb = buf ^ 1;
                    if (loadB) {
                        BsD[nb][lc + 0][lr] = make_float2(v.x, v.x);
                        BsD[nb][lc + 1][lr] = make_float2(v.y, v.y);
                        BsD[nb][lc + 2][lr] = make_float2(v.z, v.z);
                        BsD[nb][lc + 3][lr] = make_float2(v.w, v.w);
                    } else {
                        As[nb][lc + 0][lr] = v.x; As[nb][lc + 1][lr] = v.y;
                        As[nb][lc + 2][lr] = v.z; As[nb][lc + 3][lr] = v.w;
                    }
                    __syncthreads();
                }
            }
#pragma unroll
            for (int p = 0; p < 2; p++)
#pragma unroll
                for (int j = 0; j < 4; j++) ADDF2(accT[p][j], accT[p][j], accP[p][j]);

#pragma unroll
            for (int j = 0; j < 4; j++) {
                int n = bn + n0 + j;
                float alpha = g_alpha_r1[n];
                float ro    = g_ro_r1[n];
                float one_m_alpha = __fsub_rn(1.0f, alpha);
                float one_m_ro    = __fsub_rn(1.0f, ro);
                float bias  = bh2h[n];
#pragma unroll
                for (int p = 0; p < 2; p++) {
                    float lo, hi;
                    UNPACKF2(lo, hi, accT[p][j]);
#pragma unroll
                    for (int h = 0; h < 2; h++) {
                        float accv = h ? hi : lo;
                        int m = bm + m0 + 2 * p + h;
                        size_t idx = (size_t)m * HID + n;
                        float hin   = __fadd_rn(__fadd_rn(
                                          g_hin[((size_t)m * T_STEPS + t) * HID + n], accv), bias);
                        float sp    = __ldcg(&SP[idx]);
                        float bprev = (t == 0) ? BJ0 : g_r1_b[idx];
                        float mprev = (t == 0) ? r1_mem0[idx] : g_r1_mem[idx];
                        float bnew  = __fmaf_rn(ro, bprev, __fmul_rn(one_m_ro, sp));
                        float Bth   = __fmaf_rn(BETA_C, bnew, BJ0);
                        float t1    = __fmaf_rn(mprev, alpha, __fmul_rn(one_m_alpha, hin));
                        float mnew  = __fmaf_rn(-Bth, sp, t1);
                        float spn   = (__fsub_rn(mnew, Bth) > 0.0f) ? 1.0f : 0.0f;
                        g_r1_b[idx]   = bnew;
                        g_r1_mem[idx] = mnew;
                        SO[idx]       = spn;
                    }
                }
            }
        } else if (t >= 1) {
            // ---- output-layer step s = t-1 on this block's row slice ----
            int s = t - 1;
            const float* OPrev = (s == 0) ? (const float*)nullptr
                                 : (out_o ? out_o + (size_t)(s - 1) * BATCH * OUTN
                                          : g_o_spk[(s + 1) & 1]);
            float* OOut = out_o ? out_o + (size_t)s * BATCH * OUTN : g_o_spk[s & 1];
            int rIdx = bx - 128;
            int rowBase = rIdx * 52;
            int rows = (rowBase + 52 <= BATCH) ? 52 : (BATCH - rowBase);
            out_step_body(s, rowBase, rows, SP, OPrev, OOut,
                          Wd2o, bd2o, d2o_mem0, out_sum, msm);
        }

        // ---- grid-wide barrier (release/acquire via threadfence; L1 invalidated) ----
        __syncthreads();
        if (tid == 0) {
            __threadfence();
            atomicAdd(&g_bar, 1u);
            unsigned target = (unsigned)(t + 1) * NBLK;
            while (*(volatile unsigned*)&g_bar < target) { }
            __threadfence();
        }
        __syncthreads();
    }

    // ---- tail: out step s = 19, distributed over all blocks ----
    {
        int s = T_STEPS - 1;
        const float* SP = out_r1 ? out_r1 + (size_t)s * BATCH * HID : g_r1_spk[s & 1];
        const float* OPrev = out_o ? out_o + (size_t)(s - 1) * BATCH * OUTN : g_o_spk[(s + 1) & 1];
        float* OOut = out_o ? out_o + (size_t)s * BATCH * OUTN : g_o_spk[s & 1];
        int rowBase = bx * 7;
        if (rowBase < BATCH) {
            int rows = (rowBase + 7 <= BATCH) ? 7 : (BATCH - rowBase);
            out_step_body(s, rowBase, rows, SP, OPrev, OOut,
                          Wd2o, bd2o, d2o_mem0, out_sum, msm);
        }
    }
}

// ---------------- launch ----------------
extern "C" void kernel_launch(void* const* d_in, const int* in_sizes, int n_in,
                              void* d_out, int out_size) {
    const float* x          = (const float*)d_in[0];
    const float* W_i2h      = (const float*)d_in[1];
    const float* b_i2h      = (const float*)d_in[2];
    const float* W_h2h      = (const float*)d_in[3];
    const float* b_h2h      = (const float*)d_in[4];
    const float* W_d2o      = (const float*)d_in[5];
    const float* b_d2o      = (const float*)d_in[6];
    const float* tau_adp_r1 = (const float*)d_in[7];
    const float* tau_m_r1   = (const float*)d_in[8];
    const float* tau_adp_o  = (const float*)d_in[9];
    const float* tau_m_o    = (const float*)d_in[10];
    const float* r1_mem0    = (const float*)d_in[11];
    const float* r1_spike0  = (const float*)d_in[12];
    const float* d2o_mem0   = (const float*)d_in[13];
    float* out = (float*)d_out;

    const long long SUMN = (long long)BATCH * OUTN;
    const long long R1N  = (long long)T_STEPS * BATCH * HID;
    const long long ON   = (long long)T_STEPS * BATCH * OUTN;
    const bool full = ((long long)out_size >= SUMN + R1N + ON);
    float* out_r1 = full ? out + SUMN : (float*)nullptr;
    float* out_o  = full ? out + SUMN + R1N : (float*)nullptr;

    init_decay<<<1, HID>>>(tau_m_r1, tau_adp_r1, tau_m_o, tau_adp_o);

    gemm_i2h<<<dim3(HID / 64, (T_STEPS * BATCH) / 128), 256>>>(x, W_i2h, b_i2h);

    persistent_steps<<<NBLK, 256>>>(r1_spike0, W_h2h, b_h2h, r1_mem0,
                                    W_d2o, b_d2o, d2o_mem0, out,
                                    out_r1, out_o);
}

// round 15
// speedup vs baseline: 1.1999x; 1.1099x over previous
#include <cuda_runtime.h>
#include <math.h>
#include <stdint.h>

#define T_STEPS 20
#define BATCH   1024
#define D_IN    2312
#define HID     512
#define OUTN    10
#define BJ0     0.01f
#define BETA_C  1.8f
#define NBLK    296          // persistent grid: two blocks per SM, single wave
#define OROWS   26           // batch rows per out-block during the step loop

// Eigen TensorContractionBlocking (threaded): kc = (16384-192)/64 = 253 -> floor8 = 248.
// BK=8 tiles: panel fold when (tile+1) % 31 == 0.
#define KC_PANEL 248

// ---------------- device state (no allocs allowed) ----------------
__device__ float g_hin[(size_t)T_STEPS * BATCH * HID];
__device__ float g_r1_mem[BATCH * HID];
__device__ float g_r1_b[BATCH * HID];
__device__ float g_r1_spk[2][BATCH * HID];
__device__ float g_o_mem[BATCH * OUTN];
__device__ float g_o_b[BATCH * OUTN];
__device__ float g_o_spk[2][BATCH * OUTN];
__device__ float g_alpha_r1[HID], g_ro_r1[HID];
__device__ float g_alpha_o[OUTN], g_ro_o[OUTN];
__device__ unsigned g_bar;

// ---------------- packed f32x2 helpers (per-half rn semantics, proven bit-safe) ----------
#define UNPACKF2(lo, hi, s) asm("mov.b64 {%0, %1}, %2;" : "=f"(lo), "=f"(hi) : "l"(s))
#define FMAF2(acc, a, b) asm("fma.rn.f32x2 %0, %1, %2, %0;" : "+l"(acc) : "l"(a), "l"(b))
#define ADDF2(d, a, b) asm("add.rn.f32x2 %0, %1, %2;" : "=l"(d) : "l"(a), "l"(b))

// ---------------- XLA:CPU GenerateVF32Exp (frozen) ----------------
__device__ __forceinline__ float xla_expf(float input) {
    const float exp_hi = 88.3762626647950f;
    const float exp_lo = -88.3762626647949f;
    const float LOG2EF = 1.44269504088896341f;
    const float C1 = 0.693359375f;
    const float C2 = -2.12194440e-4f;
    const float p0 = 1.9875691500E-4f;
    const float p1 = 1.3981999507E-3f;
    const float p2 = 8.3334519073E-3f;
    const float p3 = 4.1665795894E-2f;
    const float p4 = 1.6666665459E-1f;
    const float p5 = 5.0000001201E-1f;

    float x = fminf(input, exp_hi);
    x = fmaxf(x, exp_lo);
    float fx = floorf(__fmaf_rn(x, LOG2EF, 0.5f));
    x = __fmaf_rn(-C1, fx, x);
    x = __fmaf_rn(-C2, fx, x);
    float z = __fmul_rn(x, x);
    float y = __fmaf_rn(x, p0, p1);
    y = __fmaf_rn(y, x, p2);
    y = __fmaf_rn(y, x, p3);
    y = __fmaf_rn(y, x, p4);
    y = __fmaf_rn(y, x, p5);
    y = __fmaf_rn(y, z, x);
    y = __fadd_rn(1.0f, y);
    int mi = (int)fx;
    float sc = __int_as_float((mi + 127) << 23);
    return fmaxf(__fmul_rn(y, sc), input);
}

__global__ void init_decay(const float* __restrict__ tau_m_r1, const float* __restrict__ tau_adp_r1,
                           const float* __restrict__ tau_m_o,  const float* __restrict__ tau_adp_o) {
    int i = threadIdx.x;
    if (i == 0) g_bar = 0u;
    if (i < HID) {
        g_alpha_r1[i] = xla_expf(__fdiv_rn(-1.0f, tau_m_r1[i]));
        g_ro_r1[i]    = xla_expf(__fdiv_rn(-1.0f, tau_adp_r1[i]));
    }
    if (i < OUTN) {
        g_alpha_o[i]  = xla_expf(__fdiv_rn(-1.0f, tau_m_o[i]));
        g_ro_o[i]     = xla_expf(__fdiv_rn(-1.0f, tau_adp_o[i]));
    }
}

// ---------------- Kernel 1: i2h GEMM, f32x2, depth-2 prefetch, kc=248 panels -------------
// M=20480, N=512, K=2312. BM=128, BN=64, BK=8, 256 threads, 4 M-pairs x 4 N per thread.
__global__ __launch_bounds__(256, 2) void gemm_i2h(const float* __restrict__ A,
                                                   const float* __restrict__ W,
                                                   const float* __restrict__ bias) {
    const int K = D_IN;
    __shared__ __align__(16) float  As[2][8][132];
    __shared__ __align__(16) float2 BsD[2][8][66];

    int bm = blockIdx.y * 128;
    int bn = blockIdx.x * 64;
    int tid = threadIdx.x;
    int wid = tid >> 5, lane = tid & 31;
    int m0 = (wid & 3) * 32 + (lane & 3) * 8;
    int n0 = (wid >> 2) * 32 + (lane >> 2) * 4;

    int alr = tid >> 1, alc = (tid & 1) * 4;
    int blr = (tid & 127) >> 1, blc = ((tid & 127) & 1) * 4;
    const float* Aptr = A + (size_t)(bm + alr) * K + alc;
    const float* Wptr = W + (size_t)(bn + blr) * K + blc;

    uint64_t accT[4][4], accP[4][4];
#pragma unroll
    for (int p = 0; p < 4; p++)
#pragma unroll
        for (int j = 0; j < 4; j++) { accT[p][j] = 0ull; accP[p][j] = 0ull; }

    const int NT = K / 8;   // 289, all tiles full
    bool isB = (tid < 128);

    // preload tile 0 -> smem buf 0; prefetch tiles 1 (Next) and 2 (Far) into regs
    {
        float4 a0 = *(const float4*)(Aptr);
        As[0][alc + 0][alr] = a0.x; As[0][alc + 1][alr] = a0.y;
        As[0][alc + 2][alr] = a0.z; As[0][alc + 3][alr] = a0.w;
        if (isB) {
            float4 b0 = *(const float4*)(Wptr);
            BsD[0][blc + 0][blr] = make_float2(b0.x, b0.x);
            BsD[0][blc + 1][blr] = make_float2(b0.y, b0.y);
            BsD[0][blc + 2][blr] = make_float2(b0.z, b0.z);
            BsD[0][blc + 3][blr] = make_float2(b0.w, b0.w);
        }
    }
    float4 aN = *(const float4*)(Aptr + 8);
    float4 bN = make_float4(0.f, 0.f, 0.f, 0.f);
    if (isB) bN = *(const float4*)(Wptr + 8);
    float4 aF = *(const float4*)(Aptr + 16);
    float4 bF = make_float4(0.f, 0.f, 0.f, 0.f);
    if (isB) bF = *(const float4*)(Wptr + 16);
    __syncthreads();

    for (int it = 0; it < NT; ++it) {
        int buf = it & 1;
#pragma unroll
        for (int kk = 0; kk < 8; kk++) {
            ulonglong2 aa0 = *(const ulonglong2*)&As[buf][kk][m0];
            ulonglong2 aa1 = *(const ulonglong2*)&As[buf][kk][m0 + 4];
            ulonglong2 bb0 = *(const ulonglong2*)&BsD[buf][kk][n0];
            ulonglong2 bb1 = *(const ulonglong2*)&BsD[buf][kk][n0 + 2];
            uint64_t ap0 = aa0.x, ap1 = aa0.y, ap2 = aa1.x, ap3 = aa1.y;
            FMAF2(accP[0][0], ap0, bb0.x); FMAF2(accP[0][1], ap0, bb0.y);
            FMAF2(accP[0][2], ap0, bb1.x); FMAF2(accP[0][3], ap0, bb1.y);
            FMAF2(accP[1][0], ap1, bb0.x); FMAF2(accP[1][1], ap1, bb0.y);
            FMAF2(accP[1][2], ap1, bb1.x); FMAF2(accP[1][3], ap1, bb1.y);
            FMAF2(accP[2][0], ap2, bb0.x); FMAF2(accP[2][1], ap2, bb0.y);
            FMAF2(accP[2][2], ap2, bb1.x); FMAF2(accP[2][3], ap2, bb1.y);
            FMAF2(accP[3][0], ap3, bb0.x); FMAF2(accP[3][1], ap3, bb0.y);
            FMAF2(accP[3][2], ap3, bb1.x); FMAF2(accP[3][3], ap3, bb1.y);
        }
        if (((it + 1) % 31) == 0) {
#pragma unroll
            for (int p = 0; p < 4; p++)
#pragma unroll
                for (int j = 0; j < 4; j++) {
                    ADDF2(accT[p][j], accT[p][j], accP[p][j]);
                    accP[p][j] = 0ull;
                }
        }
        if (it + 1 < NT) {
            int nb = buf ^ 1;
            As[nb][alc + 0][alr] = aN.x; As[nb][alc + 1][alr] = aN.y;
            As[nb][alc + 2][alr] = aN.z; As[nb][alc + 3][alr] = aN.w;
            if (isB) {
                BsD[nb][blc + 0][blr] = make_float2(bN.x, bN.x);
                BsD[nb][blc + 1][blr] = make_float2(bN.y, bN.y);
                BsD[nb][blc + 2][blr] = make_float2(bN.z, bN.z);
                BsD[nb][blc + 3][blr] = make_float2(bN.w, bN.w);
            }
            __syncthreads();
            aN = aF; bN = bF;
            if (it + 3 < NT) {
                aF = *(const float4*)(Aptr + (it + 3) * 8);
                if (isB) bF = *(const float4*)(Wptr + (it + 3) * 8);
            }
        }
    }
#pragma unroll
    for (int p = 0; p < 4; p++)
#pragma unroll
        for (int j = 0; j < 4; j++) ADDF2(accT[p][j], accT[p][j], accP[p][j]);

#pragma unroll
    for (int p = 0; p < 4; p++) {
        int r0 = bm + m0 + 2 * p;
#pragma unroll
        for (int j = 0; j < 4; j++) {
            int n = bn + n0 + j;
            float lo, hi;
            UNPACKF2(lo, hi, accT[p][j]);
            g_hin[(size_t)r0 * HID + n]       = __fadd_rn(lo, bias[n]);
            g_hin[(size_t)(r0 + 1) * HID + n] = __fadd_rn(hi, bias[n]);
        }
    }
}

// ---------------- output-layer step body (frozen semantics; cross-block reads via ldcg) --
__device__ __forceinline__ void out_step_body(
        int s, int rowBase, int rows,
        const float* __restrict__ SP, const float* __restrict__ OPrev,
        float* __restrict__ OOut,
        const float* __restrict__ Wd2o, const float* __restrict__ bd2o,
        const float* __restrict__ d2o_mem0, float* __restrict__ out_sum,
        float (*msm)[OUTN]) {
    int tid = threadIdx.x;
    for (int p = tid; p < rows * OUTN; p += 256) {
        int bl = p / OUTN, o = p - bl * OUTN;
        int b = rowBase + bl;
        const float4* s4 = (const float4*)(SP + (size_t)b * HID);
        const float4* w4 = (const float4*)(Wd2o + (size_t)o * HID);

        float a1 = 0.0f, a2 = 0.0f;
#pragma unroll 2
        for (int q = 0; q < 62; q++) {
            float4 u = __ldcg(&s4[q]);
            float4 wa = w4[q];
            float4 v = __ldcg(&s4[q + 62]);
            float4 wb = w4[q + 62];
            a1 = __fmaf_rn(u.x, wa.x, a1);
            a1 = __fmaf_rn(u.y, wa.y, a1);
            a1 = __fmaf_rn(u.z, wa.z, a1);
            a1 = __fmaf_rn(u.w, wa.w, a1);
            a2 = __fmaf_rn(v.x, wb.x, a2);
            a2 = __fmaf_rn(v.y, wb.y, a2);
            a2 = __fmaf_rn(v.z, wb.z, a2);
            a2 = __fmaf_rn(v.w, wb.w, a2);
        }
#pragma unroll
        for (int q = 124; q < 128; q++) {
            float4 v = __ldcg(&s4[q]);
            float4 wb = w4[q];
            a2 = __fmaf_rn(v.x, wb.x, a2);
            a2 = __fmaf_rn(v.y, wb.y, a2);
            a2 = __fmaf_rn(v.z, wb.z, a2);
            a2 = __fmaf_rn(v.w, wb.w, a2);
        }
        float acc = __fadd_rn(a1, a2);

        float oin   = __fadd_rn(acc, bd2o[o]);
        float alpha = g_alpha_o[o];
        float ro    = g_ro_o[o];
        size_t idx  = (size_t)b * OUTN + o;
        float sp    = (s == 0) ? 0.0f : __ldcg(&OPrev[idx]);
        float bprev = (s == 0) ? BJ0 : __ldcg(&g_o_b[idx]);
        float mprev = (s == 0) ? d2o_mem0[idx] : __ldcg(&g_o_mem[idx]);
        float bnew  = __fmaf_rn(ro, bprev, __fmul_rn(__fsub_rn(1.0f, ro), sp));
        float Bth   = __fmaf_rn(BETA_C, bnew, BJ0);
        float t1    = __fmaf_rn(mprev, alpha, __fmul_rn(__fsub_rn(1.0f, alpha), oin));
        float mnew  = __fmaf_rn(-Bth, sp, t1);
        float spn   = (__fsub_rn(mnew, Bth) > 0.0f) ? 1.0f : 0.0f;
        g_o_b[idx]   = bnew;
        g_o_mem[idx] = mnew;
        OOut[idx]    = spn;
        msm[bl][o]   = mnew;
    }
    __syncthreads();
    for (int p = tid; p < rows * OUTN; p += 256) {
        int bl = p / OUTN, o = p - bl * OUTN;
        int b = rowBase + bl;
        size_t idx = (size_t)b * OUTN + o;
        if (s == 0) {
            out_sum[idx] = 0.0f;
        } else {
            float mvals[OUTN];
#pragma unroll
            for (int q = 0; q < OUTN; q++) mvals[q] = msm[bl][q];
            float mx = mvals[0];
#pragma unroll
            for (int q = 1; q < OUTN; q++) mx = fmaxf(mx, mvals[q]);
            float e[OUTN];
#pragma unroll
            for (int q = 0; q < OUTN; q++) e[q] = xla_expf(__fsub_rn(mvals[q], mx));
            float se = 0.0f;
#pragma unroll
            for (int q = 0; q < OUTN; q++) se = __fadd_rn(se, e[q]);
            out_sum[idx] = __fadd_rn(__ldcg(&out_sum[idx]), __fdiv_rn(e[o], se));
        }
    }
}

// ---------------- persistent 20-step kernel: 296 blocks (2/SM), spin barrier -------------
// blocks 0..255: r1 GEMM tiles 32(M)x64(N) + LIF; blocks 256..295: out step (t-1).
__global__ __launch_bounds__(256, 2) void persistent_steps(
        const float* __restrict__ r1_spike0,
        const float* __restrict__ Wh2h, const float* __restrict__ bh2h,
        const float* __restrict__ r1_mem0,
        const float* __restrict__ Wd2o, const float* __restrict__ bd2o,
        const float* __restrict__ d2o_mem0, float* __restrict__ out_sum,
        float* out_r1, float* out_o) {
    __shared__ __align__(16) float  As[2][8][36];
    __shared__ __align__(16) float2 BsD[2][8][66];
    __shared__ float msm[OROWS][OUTN];

    int bx = blockIdx.x;
    int tid = threadIdx.x;

    // GEMM thread mapping (32x64 tile, 2 M-pairs x 2 N per thread)
    int wid = tid >> 5, lane = tid & 31;
    int m0 = (wid & 3) * 8 + (lane & 1) * 4;
    int n0 = (wid >> 2) * 32 + (lane >> 1) * 2;
    bool ldA = (tid < 64);
    bool ldB = (tid >= 64 && tid < 192);
    int lrA = (tid & 63) >> 1, lcA = (tid & 1) * 4;
    int uB = (tid - 64) & 127;
    int lrB = uB >> 1, lcB = (uB & 1) * 4;

    for (int t = 0; t < T_STEPS; t++) {
        const float* SP = (t == 0) ? r1_spike0
                          : (out_r1 ? out_r1 + (size_t)(t - 1) * BATCH * HID
                                    : g_r1_spk[(t + 1) & 1]);
        if (bx < 256) {
            // ---- r1 GEMM + LIF (frozen bit-exact chains; fold k=248,496) ----
            float* SO = out_r1 ? out_r1 + (size_t)t * BATCH * HID : g_r1_spk[t & 1];
            int bn = (bx & 7) * 64;
            int bm = (bx >> 3) * 32;
            const float* srcS = SP   + (size_t)(bm + lrA) * HID + lcA;
            const float* srcW = Wh2h + (size_t)(bn + lrB) * HID + lcB;

            uint64_t accT[2][2], accP[2][2];
#pragma unroll
            for (int p = 0; p < 2; p++)
#pragma unroll
                for (int j = 0; j < 2; j++) { accT[p][j] = 0ull; accP[p][j] = 0ull; }

            const int NT = HID / 8;   // 64

            float4 v = make_float4(0.f, 0.f, 0.f, 0.f);
            if (ldA) v = __ldcg((const float4*)srcS);
            else if (ldB) v = *(const float4*)srcW;
            if (ldA) {
                As[0][lcA + 0][lrA] = v.x; As[0][lcA + 1][lrA] = v.y;
                As[0][lcA + 2][lrA] = v.z; As[0][lcA + 3][lrA] = v.w;
            } else if (ldB) {
                BsD[0][lcB + 0][lrB] = make_float2(v.x, v.x);
                BsD[0][lcB + 1][lrB] = make_float2(v.y, v.y);
                BsD[0][lcB + 2][lrB] = make_float2(v.z, v.z);
                BsD[0][lcB + 3][lrB] = make_float2(v.w, v.w);
            }
            __syncthreads();

            for (int it = 0; it < NT; ++it) {
                int buf = it & 1;
                if (it + 1 < NT) {
                    if (ldA) v = __ldcg((const float4*)(srcS + (it + 1) * 8));
                    else if (ldB) v = *(const float4*)(srcW + (it + 1) * 8);
                }
#pragma unroll
                for (int kk = 0; kk < 8; kk++) {
                    ulonglong2 aa = *(const ulonglong2*)&As[buf][kk][m0];
                    ulonglong2 bb = *(const ulonglong2*)&BsD[buf][kk][n0];
                    FMAF2(accP[0][0], aa.x, bb.x); FMAF2(accP[0][1], aa.x, bb.y);
                    FMAF2(accP[1][0], aa.y, bb.x); FMAF2(accP[1][1], aa.y, bb.y);
                }
                if (((it + 1) % 31) == 0) {
#pragma unroll
                    for (int p = 0; p < 2; p++)
#pragma unroll
                        for (int j = 0; j < 2; j++) {
                            ADDF2(accT[p][j], accT[p][j], accP[p][j]);
                            accP[p][j] = 0ull;
                        }
                }
                if (it + 1 < NT) {
                    int nb = buf ^ 1;
                    if (ldA) {
                        As[nb][lcA + 0][lrA] = v.x; As[nb][lcA + 1][lrA] = v.y;
                        As[nb][lcA + 2][lrA] = v.z; As[nb][lcA + 3][lrA] = v.w;
                    } else if (ldB) {
                        BsD[nb][lcB + 0][lrB] = make_float2(v.x, v.x);
                        BsD[nb][lcB + 1][lrB] = make_float2(v.y, v.y);
                        BsD[nb][lcB + 2][lrB] = make_float2(v.z, v.z);
                        BsD[nb][lcB + 3][lrB] = make_float2(v.w, v.w);
                    }
                    __syncthreads();
                }
            }
#pragma unroll
            for (int p = 0; p < 2; p++)
#pragma unroll
                for (int j = 0; j < 2; j++) ADDF2(accT[p][j], accT[p][j], accP[p][j]);

#pragma unroll
            for (int j = 0; j < 2; j++) {
                int n = bn + n0 + j;
                float alpha = g_alpha_r1[n];
                float ro    = g_ro_r1[n];
                float one_m_alpha = __fsub_rn(1.0f, alpha);
                float one_m_ro    = __fsub_rn(1.0f, ro);
                float bias  = bh2h[n];
#pragma unroll
                for (int p = 0; p < 2; p++) {
                    float lo, hi;
                    UNPACKF2(lo, hi, accT[p][j]);
#pragma unroll
                    for (int h = 0; h < 2; h++) {
                        float accv = h ? hi : lo;
                        int m = bm + m0 + 2 * p + h;
                        size_t idx = (size_t)m * HID + n;
                        float hin   = __fadd_rn(__fadd_rn(
                                          g_hin[((size_t)m * T_STEPS + t) * HID + n], accv), bias);
                        float sp    = __ldcg(&SP[idx]);
                        float bprev = (t == 0) ? BJ0 : g_r1_b[idx];
                        float mprev = (t == 0) ? r1_mem0[idx] : g_r1_mem[idx];
                        float bnew  = __fmaf_rn(ro, bprev, __fmul_rn(one_m_ro, sp));
                        float Bth   = __fmaf_rn(BETA_C, bnew, BJ0);
                        float t1    = __fmaf_rn(mprev, alpha, __fmul_rn(one_m_alpha, hin));
                        float mnew  = __fmaf_rn(-Bth, sp, t1);
                        float spn   = (__fsub_rn(mnew, Bth) > 0.0f) ? 1.0f : 0.0f;
                        g_r1_b[idx]   = bnew;
                        g_r1_mem[idx] = mnew;
                        SO[idx]       = spn;
                    }
                }
            }
        } else if (t >= 1) {
            // ---- output-layer step s = t-1 ----
            int s = t - 1;
            const float* OPrev = (s == 0) ? (const float*)nullptr
                                 : (out_o ? out_o + (size_t)(s - 1) * BATCH * OUTN
                                          : g_o_spk[(s + 1) & 1]);
            float* OOut = out_o ? out_o + (size_t)s * BATCH * OUTN : g_o_spk[s & 1];
            int rowBase = (bx - 256) * OROWS;
            if (rowBase < BATCH) {
                int rows = (rowBase + OROWS <= BATCH) ? OROWS : (BATCH - rowBase);
                out_step_body(s, rowBase, rows, SP, OPrev, OOut,
                              Wd2o, bd2o, d2o_mem0, out_sum, msm);
            }
        }

        // ---- grid-wide barrier (release/acquire) ----
        __syncthreads();
        if (tid == 0) {
            __threadfence();
            atomicAdd(&g_bar, 1u);
            unsigned target = (unsigned)(t + 1) * NBLK;
            while (*(volatile unsigned*)&g_bar < target) { }
            __threadfence();
        }
        __syncthreads();
    }

    // ---- tail: out step s = 19, distributed over blocks 0..255 (4 rows each) ----
    {
        int s = T_STEPS - 1;
        int rowBase = bx * 4;
        if (rowBase < BATCH) {
            const float* SP = out_r1 ? out_r1 + (size_t)s * BATCH * HID : g_r1_spk[s & 1];
            const float* OPrev = out_o ? out_o + (size_t)(s - 1) * BATCH * OUTN
                                       : g_o_spk[(s + 1) & 1];
            float* OOut = out_o ? out_o + (size_t)s * BATCH * OUTN : g_o_spk[s & 1];
            int rows = (rowBase + 4 <= BATCH) ? 4 : (BATCH - rowBase);
            out_step_body(s, rowBase, rows, SP, OPrev, OOut,
                          Wd2o, bd2o, d2o_mem0, out_sum, msm);
        }
    }
}

// ---------------- launch ----------------
extern "C" void kernel_launch(void* const* d_in, const int* in_sizes, int n_in,
                              void* d_out, int out_size) {
    const float* x          = (const float*)d_in[0];
    const float* W_i2h      = (const float*)d_in[1];
    const float* b_i2h      = (const float*)d_in[2];
    const float* W_h2h      = (const float*)d_in[3];
    const float* b_h2h      = (const float*)d_in[4];
    const float* W_d2o      = (const float*)d_in[5];
    const float* b_d2o      = (const float*)d_in[6];
    const float* tau_adp_r1 = (const float*)d_in[7];
    const float* tau_m_r1   = (const float*)d_in[8];
    const float* tau_adp_o  = (const float*)d_in[9];
    const float* tau_m_o    = (const float*)d_in[10];
    const float* r1_mem0    = (const float*)d_in[11];
    const float* r1_spike0  = (const float*)d_in[12];
    const float* d2o_mem0   = (const float*)d_in[13];
    float* out = (float*)d_out;

    const long long SUMN = (long long)BATCH * OUTN;
    const long long R1N  = (long long)T_STEPS * BATCH * HID;
    const long long ON   = (long long)T_STEPS * BATCH * OUTN;
    const bool full = ((long long)out_size >= SUMN + R1N + ON);
    float* out_r1 = full ? out + SUMN : (float*)nullptr;
    float* out_o  = full ? out + SUMN + R1N : (float*)nullptr;

    init_decay<<<1, HID>>>(tau_m_r1, tau_adp_r1, tau_m_o, tau_adp_o);

    gemm_i2h<<<dim3(HID / 64, (T_STEPS * BATCH) / 128), 256>>>(x, W_i2h, b_i2h);

    persistent_steps<<<NBLK, 256>>>(r1_spike0, W_h2h, b_h2h, r1_mem0,
                                    W_d2o, b_d2o, d2o_mem0, out,
                                    out_r1, out_o);
}